// round 6
// baseline (speedup 1.0000x reference)
#include <cuda_runtime.h>
#include <cuda_bf16.h>
#include <math.h>
#include <mma.h>

using namespace nvcuda;

// ---------------------------------------------------------------------------
// ScaffoldGAN JTNN GRU + discriminator. R6: 3xTF32 compensated WMMA GEMMs.
//   * wmma_gemm: 128x128x16 double-buffered; per k-step each product is
//     a_lo*w_hi + a_hi*w_lo + a_hi*w_hi  (hi/lo split in registers) ->
//     fp32-grade accuracy on the tensor pipe (single-pass TF32 failed 1.2e-3).
//   * All wmma operands in padded 16B-aligned scratch.
//   * Biases folded into elementwise consumers; GRU epilogue in h_update.
//   * Discriminator on fp32 SIMT GEMM (exact, tiny).
// ---------------------------------------------------------------------------

#define HH     450
#define NNODES 4000
#define NMESS  6000
#define KNB    6
#define BB     256
#define DHH    450
#define MAXDEPTH 15
#define MROWS  6016

#define LDX   512
#define LDZU  1024
#define LDPRE 1536

// ---------------- device scratch ------------------
__device__ float g_fe[NNODES * HH];
__device__ float g_x[MROWS * LDX];
__device__ float g_xzrh[MROWS * LDPRE];
__device__ float g_h[MROWS * LDX];
__device__ float g_hZU[MROWS * LDZU];
__device__ float g_sumh[MROWS * LDX];
__device__ float g_z[MROWS * LDX];
__device__ float g_sumgh[MROWS * LDX];
__device__ float g_preh[MROWS * LDX];
__device__ float g_Wpre[1350 * LDX];
__device__ float g_Wstep[900 * LDX];
__device__ float g_Whh[HH * LDX];
__device__ float g_bias[1536];
__device__ float g_rv[BB * 2 * HH];
__device__ float g_d1[BB * DHH];
__device__ float g_d2[BB * DHH];

// ---------------------------- small kernels --------------------------------
__global__ void zero_kernel(float* p, int n) {
    int i = blockIdx.x * blockDim.x + threadIdx.x;
    if (i < n) p[i] = 0.f;
}

__global__ void pack_kernel(const float* __restrict__ W_z_w,
                            const float* __restrict__ W_h_w,
                            const float* __restrict__ W_r_w,
                            const float* __restrict__ U_r_w,
                            const float* __restrict__ W_z_b,
                            const float* __restrict__ W_h_b,
                            const float* __restrict__ U_r_b,
                            float* __restrict__ Wpre,
                            float* __restrict__ Wstep,
                            float* __restrict__ Whh,
                            float* __restrict__ bias) {
    int i = blockIdx.x * blockDim.x + threadIdx.x;
    const int NPRE  = 1350 * HH;
    const int NSTEP = 900 * HH;
    const int NWHH  = HH * HH;
    if (i < NPRE) {
        int n = i / HH, k = i - n * HH;
        float v;
        if (n < HH)            v = W_z_w[n * 2 * HH + k];
        else if (n < 2 * HH)   v = W_h_w[(n - HH) * 2 * HH + k];
        else                   v = W_r_w[(n - 2 * HH) * HH + k];
        Wpre[n * LDX + k] = v;
    } else if (i < NPRE + NSTEP) {
        int j = i - NPRE;
        int n = j / HH, k = j - n * HH;
        float v = (n < HH) ? W_z_w[n * 2 * HH + HH + k]
                           : U_r_w[(n - HH) * HH + k];
        Wstep[n * LDX + k] = v;
    } else if (i < NPRE + NSTEP + NWHH) {
        int j = i - NPRE - NSTEP;
        int n = j / HH, k = j - n * HH;
        Whh[n * LDX + k] = W_h_w[n * 2 * HH + HH + k];
    } else if (i < NPRE + NSTEP + NWHH + 1350) {
        int n = i - NPRE - NSTEP - NWHH;
        bias[n] = (n < HH) ? W_z_b[n]
                : (n < 2 * HH) ? W_h_b[n - HH]
                : U_r_b[n - 2 * HH];
    }
}

__global__ void gather_fe_kernel(const float* __restrict__ emb,
                                 const int* __restrict__ fnode,
                                 float* __restrict__ fe) {
    int i = blockIdx.x * blockDim.x + threadIdx.x;
    if (i >= NNODES * HH) return;
    int r = i / HH, c = i - r * HH;
    fe[i] = emb[fnode[r] * HH + c];
}

__global__ void gather_x_kernel(const float* __restrict__ fe,
                                const int* __restrict__ fmess,
                                float* __restrict__ x) {
    int i = blockIdx.x * blockDim.x + threadIdx.x;
    if (i >= NMESS * HH) return;
    int r = i / HH, c = i - r * HH;
    x[r * LDX + c] = fe[fmess[r] * HH + c];
}

__device__ __forceinline__ float2 sigm2(float2 v) {
    return make_float2(1.f / (1.f + __expf(-v.x)), 1.f / (1.f + __expf(-v.y)));
}
__device__ __forceinline__ float2 tanh2(float2 v) {
    return make_float2(tanhf(v.x), tanhf(v.y));
}

#define C2 225

__global__ void step0_kernel(const float* __restrict__ xzrh,
                             const float* __restrict__ bias,
                             float* __restrict__ h,
                             const int* __restrict__ depthp) {
    if (depthp && __ldg(depthp) < 1) return;
    int i = blockIdx.x * blockDim.x + threadIdx.x;
    if (i >= NMESS * C2) return;
    int m = i / C2, c = i - m * C2;
    const float2* xp = (const float2*)xzrh + (size_t)m * (LDPRE / 2);
    const float2* bp = (const float2*)bias;
    float2 xz = xp[c],        bz = bp[c];
    float2 xh = xp[C2 + c],   bh = bp[C2 + c];
    float2 zv = sigm2(make_float2(xz.x + bz.x, xz.y + bz.y));
    float2 ph = tanh2(make_float2(xh.x + bh.x, xh.y + bh.y));
    float2 v = make_float2(zv.x * ph.x, zv.y * ph.y);
    if (m == 0) v = make_float2(0.f, 0.f);
    ((float2*)h)[(size_t)m * (LDX / 2) + c] = v;
}

__global__ void step_gather_kernel(const float* __restrict__ h,
                                   const float* __restrict__ hZU,
                                   const float* __restrict__ xzrh,
                                   const float* __restrict__ bias,
                                   const int* __restrict__ mg,
                                   float* __restrict__ sumh,
                                   float* __restrict__ z,
                                   float* __restrict__ sumgh,
                                   const int* __restrict__ depthp, int step) {
    if (depthp && step >= __ldg(depthp)) return;
    int i = blockIdx.x * blockDim.x + threadIdx.x;
    if (i >= NMESS * C2) return;
    int m = i / C2, c = i - m * C2;
    const float2* xp = (const float2*)xzrh + (size_t)m * (LDPRE / 2);
    const float2* bp = (const float2*)bias;
    float2 xr = xp[2 * C2 + c], br = bp[2 * C2 + c];
    float xr0 = xr.x + br.x, xr1 = xr.y + br.y;
    float2 sh = make_float2(0.f, 0.f);
    float2 sz = make_float2(0.f, 0.f);
    float2 sg = make_float2(0.f, 0.f);
    int idx[KNB];
#pragma unroll
    for (int k = 0; k < KNB; k++) idx[k] = mg[m * KNB + k];
#pragma unroll
    for (int k = 0; k < KNB; k++) {
        int j = idx[k];
        float2 hv = ((const float2*)h)[(size_t)j * (LDX / 2) + c];
        float2 zz = ((const float2*)hZU)[(size_t)j * (LDZU / 2) + c];
        float2 uu = ((const float2*)hZU)[(size_t)j * (LDZU / 2) + C2 + c];
        sh.x += hv.x; sh.y += hv.y;
        sz.x += zz.x; sz.y += zz.y;
        sg.x += hv.x / (1.f + __expf(-(xr0 + uu.x)));
        sg.y += hv.y / (1.f + __expf(-(xr1 + uu.y)));
    }
    size_t o = (size_t)m * (LDX / 2) + c;
    ((float2*)sumh)[o] = sh;
    float2 xz = xp[c], bz = bp[c];
    ((float2*)z)[o] = sigm2(make_float2(sz.x + xz.x + bz.x, sz.y + xz.y + bz.y));
    ((float2*)sumgh)[o] = sg;
}

__global__ void h_update_kernel(const float* __restrict__ preh,
                                const float* __restrict__ xzrh,
                                const float* __restrict__ bias,
                                const float* __restrict__ z,
                                const float* __restrict__ sumh,
                                float* __restrict__ h,
                                const int* __restrict__ depthp, int step) {
    if (depthp && step >= __ldg(depthp)) return;
    int i = blockIdx.x * blockDim.x + threadIdx.x;
    if (i >= NMESS * C2) return;
    int m = i / C2, c = i - m * C2;
    size_t o = (size_t)m * (LDX / 2) + c;
    float2 pv = ((const float2*)preh)[o];
    float2 xh = ((const float2*)xzrh)[(size_t)m * (LDPRE / 2) + C2 + c];
    float2 bh = ((const float2*)bias)[C2 + c];
    float2 ph = tanh2(make_float2(pv.x + xh.x + bh.x, pv.y + xh.y + bh.y));
    float2 zv = ((const float2*)z)[o];
    float2 sh = ((const float2*)sumh)[o];
    float2 v = make_float2((1.f - zv.x) * sh.x + zv.x * ph.x,
                           (1.f - zv.y) * sh.y + zv.y * ph.y);
    if (m == 0) v = make_float2(0.f, 0.f);
    ((float2*)h)[o] = v;
}

__global__ void readout_kernel(const float* __restrict__ fe,
                               const float* __restrict__ h,
                               const int* __restrict__ root,
                               const int* __restrict__ ng,
                               float* __restrict__ rv) {
    int i = blockIdx.x * blockDim.x + threadIdx.x;
    if (i >= BB * HH) return;
    int b = i / HH, c = i - b * HH;
    int node = root[b];
    rv[b * 2 * HH + c] = fe[node * HH + c];
    float s = 0.f;
#pragma unroll
    for (int k = 0; k < KNB; k++)
        s += h[(size_t)ng[node * KNB + k] * LDX + c];
    rv[b * 2 * HH + HH + c] = s;
}

__global__ void score_kernel(const float* __restrict__ h2,
                             const float* __restrict__ w,
                             const float* __restrict__ b3,
                             float* __restrict__ out) {
    int gt = blockIdx.x * blockDim.x + threadIdx.x;
    int warp = gt >> 5, lane = gt & 31;
    if (warp >= BB) return;
    float s = 0.f;
    for (int k = lane; k < DHH; k += 32) s += h2[warp * DHH + k] * w[k];
#pragma unroll
    for (int o = 16; o; o >>= 1) s += __shfl_xor_sync(0xffffffffu, s, o);
    if (lane == 0) out[warp] = s + b3[0];
}

// ----------------------- 3xTF32 compensated WMMA GEMM ----------------------
// C = A @ W^T, fp32-grade accuracy on tensor pipe.
#define WBM 128
#define WBN 128
#define WBK 16
#define KPAD 20

__device__ __forceinline__ float4 ldg4_guard(const float* __restrict__ p,
                                             int row, int gk,
                                             int maxr, int K, int ld) {
    float4 v = make_float4(0.f, 0.f, 0.f, 0.f);
    if (row < maxr) {
        const float* q = p + (size_t)row * ld + gk;
        if (gk + 4 <= K) {
            v = *reinterpret_cast<const float4*>(q);
        } else {
            if (gk     < K) v.x = q[0];
            if (gk + 1 < K) v.y = q[1];
            if (gk + 2 < K) v.z = q[2];
            if (gk + 3 < K) v.w = q[3];
        }
    }
    return v;
}

__global__ __launch_bounds__(256)
void wmma_gemm(const float* __restrict__ A, int lda,
               const float* __restrict__ W, int ldw,
               int M, int N, int K,
               float* __restrict__ C, int ldc,
               const int* __restrict__ depthp, int step) {
    if (depthp && step >= __ldg(depthp)) return;

    __shared__ float As[2][WBM][KPAD];
    __shared__ float Ws[2][WBN][KPAD];

    const int tid = threadIdx.x;
    const int wid = tid >> 5;
    const int wm = wid & 1;
    const int wn = wid >> 1;
    const int bm = blockIdx.y * WBM;
    const int bn = blockIdx.x * WBN;

    wmma::fragment<wmma::accumulator, 16, 16, 8, float> acc[4][2];
#pragma unroll
    for (int i = 0; i < 4; i++)
#pragma unroll
        for (int j = 0; j < 2; j++) wmma::fill_fragment(acc[i][j], 0.f);

    int rr[2], kq[2];
#pragma unroll
    for (int t = 0; t < 2; t++) {
        int q = tid + t * 256;
        rr[t] = q >> 2;
        kq[t] = (q & 3) << 2;
    }

    const int NT = (K + WBK - 1) / WBK;

#pragma unroll
    for (int t = 0; t < 2; t++) {
        float4 va = ldg4_guard(A, bm + rr[t], kq[t], M, K, lda);
        *reinterpret_cast<float4*>(&As[0][rr[t]][kq[t]]) = va;
        float4 vw = ldg4_guard(W, bn + rr[t], kq[t], N, K, ldw);
        *reinterpret_cast<float4*>(&Ws[0][rr[t]][kq[t]]) = vw;
    }
    __syncthreads();

    for (int t0 = 0; t0 < NT; t0++) {
        const int cur = t0 & 1, nxt = cur ^ 1;
        float4 ra[2], rw[2];
        const bool more = (t0 + 1 < NT);
        if (more) {
            int k0 = (t0 + 1) * WBK;
#pragma unroll
            for (int t = 0; t < 2; t++) {
                ra[t] = ldg4_guard(A, bm + rr[t], k0 + kq[t], M, K, lda);
                rw[t] = ldg4_guard(W, bn + rr[t], k0 + kq[t], N, K, ldw);
            }
        }
#pragma unroll
        for (int kk = 0; kk < WBK; kk += 8) {
            // B hi/lo fragments for this k-step (shared across all i)
            wmma::fragment<wmma::matrix_b, 16, 16, 8, wmma::precision::tf32,
                           wmma::col_major> bhi[2], blo[2];
#pragma unroll
            for (int j = 0; j < 2; j++) {
                wmma::load_matrix_sync(bhi[j], &Ws[cur][wn * 32 + j * 16][kk], KPAD);
#pragma unroll
                for (int e = 0; e < bhi[j].num_elements; e++) {
                    float f = bhi[j].x[e];
                    float fh = wmma::__float_to_tf32(f);
                    bhi[j].x[e] = fh;
                    blo[j].x[e] = wmma::__float_to_tf32(f - fh);
                }
            }
#pragma unroll
            for (int i = 0; i < 4; i++) {
                wmma::fragment<wmma::matrix_a, 16, 16, 8, wmma::precision::tf32,
                               wmma::row_major> ahi, alo;
                wmma::load_matrix_sync(ahi, &As[cur][wm * 64 + i * 16][kk], KPAD);
#pragma unroll
                for (int e = 0; e < ahi.num_elements; e++) {
                    float f = ahi.x[e];
                    float fh = wmma::__float_to_tf32(f);
                    ahi.x[e] = fh;
                    alo.x[e] = wmma::__float_to_tf32(f - fh);
                }
#pragma unroll
                for (int j = 0; j < 2; j++) {
                    wmma::mma_sync(acc[i][j], alo, bhi[j], acc[i][j]);
                    wmma::mma_sync(acc[i][j], ahi, blo[j], acc[i][j]);
                    wmma::mma_sync(acc[i][j], ahi, bhi[j], acc[i][j]);
                }
            }
        }
        if (more) {
#pragma unroll
            for (int t = 0; t < 2; t++) {
                *reinterpret_cast<float4*>(&As[nxt][rr[t]][kq[t]]) = ra[t];
                *reinterpret_cast<float4*>(&Ws[nxt][rr[t]][kq[t]]) = rw[t];
            }
        }
        __syncthreads();
    }

#pragma unroll
    for (int i = 0; i < 4; i++)
#pragma unroll
        for (int j = 0; j < 2; j++) {
            float* cp = C + (size_t)(bm + wm * 64 + i * 16) * ldc
                          + bn + wn * 32 + j * 16;
            wmma::store_matrix_sync(cp, acc[i][j], ldc, wmma::mem_row_major);
        }
}

// ------------------ fp32 SIMT GEMM (discriminator only) --------------------
#define BM 64
#define BN 64
#define BKK 16
#define TMs 4
#define TNs 4

__global__ __launch_bounds__(256)
void disc_gemm(const float* __restrict__ A, int lda,
               const float* __restrict__ W, int ldw,
               int M, int N, int K,
               const float* __restrict__ bias,
               float* __restrict__ C, int ldc) {
    __shared__ float As[BKK][BM];
    __shared__ float Ws[BKK][BN];
    int bm = blockIdx.y * BM, bn = blockIdx.x * BN;
    int tid = threadIdx.x;
    int tr = tid >> 4, tc = tid & 15;
    float acc[TMs][TNs];
#pragma unroll
    for (int i = 0; i < TMs; i++)
#pragma unroll
        for (int j = 0; j < TNs; j++) acc[i][j] = 0.f;
    for (int k0 = 0; k0 < K; k0 += BKK) {
#pragma unroll
        for (int t = 0; t < 4; t++) {
            int l = tid + t * 256;
            int i = l >> 4, j = l & 15;
            int gm = bm + i, gk = k0 + j;
            As[j][i] = (gm < M && gk < K) ? A[(size_t)gm * lda + gk] : 0.f;
        }
#pragma unroll
        for (int t = 0; t < 4; t++) {
            int l = tid + t * 256;
            int i = l >> 4, j = l & 15;
            int gn = bn + i, gk = k0 + j;
            Ws[j][i] = (gn < N && gk < K) ? W[(size_t)gn * ldw + gk] : 0.f;
        }
        __syncthreads();
#pragma unroll
        for (int kk = 0; kk < BKK; kk++) {
            float a[TMs], w[TNs];
#pragma unroll
            for (int i = 0; i < TMs; i++) a[i] = As[kk][tr * TMs + i];
#pragma unroll
            for (int j = 0; j < TNs; j++) w[j] = Ws[kk][tc * TNs + j];
#pragma unroll
            for (int i = 0; i < TMs; i++)
#pragma unroll
                for (int j = 0; j < TNs; j++) acc[i][j] += a[i] * w[j];
        }
        __syncthreads();
    }
#pragma unroll
    for (int i = 0; i < TMs; i++) {
        int m = bm + tr * TMs + i;
        if (m >= M) continue;
#pragma unroll
        for (int j = 0; j < TNs; j++) {
            int n = bn + tc * TNs + j;
            if (n >= N) continue;
            float v = acc[i][j] + bias[n];
            v = (v > 0.f) ? v : 0.1f * v;
            C[(size_t)m * ldc + n] = v;
        }
    }
}

// ------------------------------- launcher ----------------------------------
static inline dim3 wgrid(int M, int N) {
    return dim3((N + WBN - 1) / WBN, (M + WBM - 1) / WBM);
}

extern "C" void kernel_launch(void* const* d_in, const int* in_sizes, int n_in,
                              void* d_out, int out_size) {
    const int*   fnode      = (const int*)d_in[0];
    const int*   fmess      = (const int*)d_in[1];
    const int*   node_graph = (const int*)d_in[2];
    const int*   mess_graph = (const int*)d_in[3];
    const int*   root_idx   = (const int*)d_in[4];
    const float* emb        = (const float*)d_in[5];
    const float* W_z_w      = (const float*)d_in[6];
    const float* W_z_b      = (const float*)d_in[7];
    const float* W_r_w      = (const float*)d_in[8];
    const float* U_r_w      = (const float*)d_in[9];
    const float* U_r_b      = (const float*)d_in[10];
    const float* W_h_w      = (const float*)d_in[11];
    const float* W_h_b      = (const float*)d_in[12];
    const float* D1_w       = (const float*)d_in[13];
    const float* D1_b       = (const float*)d_in[14];
    const float* D2_w       = (const float*)d_in[15];
    const float* D2_b       = (const float*)d_in[16];
    const float* D3_w       = (const float*)d_in[17];
    const float* D3_b       = (const float*)d_in[18];
    const int*   depthp     = (n_in > 19) ? (const int*)d_in[19] : nullptr;
    float*       out        = (float*)d_out;

    float *fe, *x, *xzrh, *h, *hZU, *sumh, *z, *sumgh, *preh;
    float *Wpre, *Wstep, *Whh, *bias, *rv, *d1, *d2;
    cudaGetSymbolAddress((void**)&fe,    g_fe);
    cudaGetSymbolAddress((void**)&x,     g_x);
    cudaGetSymbolAddress((void**)&xzrh,  g_xzrh);
    cudaGetSymbolAddress((void**)&h,     g_h);
    cudaGetSymbolAddress((void**)&hZU,   g_hZU);
    cudaGetSymbolAddress((void**)&sumh,  g_sumh);
    cudaGetSymbolAddress((void**)&z,     g_z);
    cudaGetSymbolAddress((void**)&sumgh, g_sumgh);
    cudaGetSymbolAddress((void**)&preh,  g_preh);
    cudaGetSymbolAddress((void**)&Wpre,  g_Wpre);
    cudaGetSymbolAddress((void**)&Wstep, g_Wstep);
    cudaGetSymbolAddress((void**)&Whh,   g_Whh);
    cudaGetSymbolAddress((void**)&bias,  g_bias);
    cudaGetSymbolAddress((void**)&rv,    g_rv);
    cudaGetSymbolAddress((void**)&d1,    g_d1);
    cudaGetSymbolAddress((void**)&d2,    g_d2);

    const int TPB = 256;

    zero_kernel<<<(MROWS * LDX + TPB - 1) / TPB, TPB>>>(h, MROWS * LDX);

    {
        int n = 1350 * HH + 900 * HH + HH * HH + 1350;
        pack_kernel<<<(n + TPB - 1) / TPB, TPB>>>(W_z_w, W_h_w, W_r_w, U_r_w,
                                                  W_z_b, W_h_b, U_r_b,
                                                  Wpre, Wstep, Whh, bias);
    }

    gather_fe_kernel<<<(NNODES * HH + TPB - 1) / TPB, TPB>>>(emb, fnode, fe);
    gather_x_kernel<<<(NMESS * HH + TPB - 1) / TPB, TPB>>>(fe, fmess, x);

    wmma_gemm<<<wgrid(NMESS, 1350), 256>>>(x, LDX, Wpre, LDX,
                                           NMESS, 1350, HH, xzrh, LDPRE,
                                           nullptr, 0);

    step0_kernel<<<(NMESS * C2 + TPB - 1) / TPB, TPB>>>(xzrh, bias, h, depthp);

    for (int s = 1; s < MAXDEPTH; s++) {
        wmma_gemm<<<wgrid(NMESS, 900), 256>>>(h, LDX, Wstep, LDX,
                                              NMESS, 900, HH, hZU, LDZU,
                                              depthp, s);
        step_gather_kernel<<<(NMESS * C2 + TPB - 1) / TPB, TPB>>>(
            h, hZU, xzrh, bias, mess_graph, sumh, z, sumgh, depthp, s);
        wmma_gemm<<<wgrid(NMESS, HH), 256>>>(sumgh, LDX, Whh, LDX,
                                             NMESS, HH, HH, preh, LDX,
                                             depthp, s);
        h_update_kernel<<<(NMESS * C2 + TPB - 1) / TPB, TPB>>>(
            preh, xzrh, bias, z, sumh, h, depthp, s);
    }

    readout_kernel<<<(BB * HH + TPB - 1) / TPB, TPB>>>(fe, h, root_idx, node_graph, rv);
    disc_gemm<<<dim3((DHH + BN - 1) / BN, (BB + BM - 1) / BM), 256>>>(
        rv, 2 * HH, D1_w, 2 * HH, BB, DHH, 2 * HH, D1_b, d1, DHH);
    disc_gemm<<<dim3((DHH + BN - 1) / BN, (BB + BM - 1) / BM), 256>>>(
        d1, DHH, D2_w, DHH, BB, DHH, DHH, D2_b, d2, DHH);
    score_kernel<<<(BB * 32 + TPB - 1) / TPB, TPB>>>(d2, D3_w, D3_b, out);
}